// round 12
// baseline (speedup 1.0000x reference)
#include <cuda_runtime.h>
#include <cuda_fp16.h>
#include <cstdint>
#include <cstddef>

// ---------------------------------------------------------------------------
// ConvVAE2d via mma.sync GEMMs (baseline sm_103 PTX).
// R12: dec2 switched to int8 IMMA (m16n8k32.s8, probe: 2x fp16 rate?) with
// per-tensor dynamic quantization (deterministic amax). enc1/enc2/dec1 stay
// fp16 f32-acc (R11 config: 512 thr, BM=128 BN=256, warp 64x32).
// ---------------------------------------------------------------------------

#define TOK 16384
#define PD  768
#define HD  2048
#define L2D 512
#define LDIM 256

// ----------------------------- scratch -------------------------------------
__device__ __align__(256) __half  g_p[TOK * PD];
__device__ __align__(256) __half  g_he[TOK * HD];
__device__ __align__(256) float   g_ml[TOK * L2D];
__device__ __align__(256) __half  g_mu[TOK * LDIM];
__device__ __align__(256) __half  g_hd[TOK * HD];
__device__ __align__(256) int8_t  g_hd8[TOK * HD];
__device__ __align__(256) __half  g_w1t[HD * PD];
__device__ __align__(256) __half  g_w2t[L2D * HD];
__device__ __align__(256) __half  g_w3t[HD * LDIM];
__device__ __align__(256) int8_t  g_w4t8[PD * HD];
__device__ __align__(256) unsigned g_scales[2];   // 0: amax(w_dec2), 1: amax(hd)

// ----------------------------- helpers -------------------------------------
__device__ __forceinline__ uint32_t smem_u32(const void* p) {
    uint32_t a;
    asm("{ .reg .u64 t; cvta.to.shared.u64 t, %1; cvt.u32.u64 %0, t; }"
        : "=r"(a) : "l"(p));
    return a;
}

#define SWZ128(o) ((uint32_t)(o) ^ ((((uint32_t)(o)) >> 3) & 0x70u))

__device__ __forceinline__ void cp16(uint32_t dst, const void* src) {
    asm volatile("cp.async.cg.shared.global [%0], [%1], 16;"
                 :: "r"(dst), "l"(src) : "memory");
}
__device__ __forceinline__ void ldsm_x4(uint32_t* r, uint32_t addr) {
    asm volatile("ldmatrix.sync.aligned.m8n8.x4.shared.b16 {%0,%1,%2,%3}, [%4];"
                 : "=r"(r[0]), "=r"(r[1]), "=r"(r[2]), "=r"(r[3]) : "r"(addr));
}
__device__ __forceinline__ void mma16816(float* c, const uint32_t* a,
                                         uint32_t b0, uint32_t b1) {
    asm volatile(
        "mma.sync.aligned.m16n8k16.row.col.f32.f16.f16.f32 "
        "{%0,%1,%2,%3}, {%4,%5,%6,%7}, {%8,%9}, {%0,%1,%2,%3};"
        : "+f"(c[0]), "+f"(c[1]), "+f"(c[2]), "+f"(c[3])
        : "r"(a[0]), "r"(a[1]), "r"(a[2]), "r"(a[3]), "r"(b0), "r"(b1));
}
// int8 IMMA: same fragment byte-layout as f16 k16 -> identical ldmatrix code.
__device__ __forceinline__ void mma16832s8(int* c, const uint32_t* a,
                                           uint32_t b0, uint32_t b1) {
    asm volatile(
        "mma.sync.aligned.m16n8k32.row.col.s32.s8.s8.s32 "
        "{%0,%1,%2,%3}, {%4,%5,%6,%7}, {%8,%9}, {%0,%1,%2,%3};"
        : "+r"(c[0]), "+r"(c[1]), "+r"(c[2]), "+r"(c[3])
        : "r"(a[0]), "r"(a[1]), "r"(a[2]), "r"(a[3]), "r"(b0), "r"(b1));
}
__device__ __forceinline__ void atomic_amax(unsigned* slot, float v) {
    // warp-reduce then one atomic per warp (v >= 0 -> uint-ordered)
    #pragma unroll
    for (int s = 16; s > 0; s >>= 1)
        v = fmaxf(v, __shfl_xor_sync(0xFFFFFFFFu, v, s));
    if ((threadIdx.x & 31) == 0) atomicMax(slot, __float_as_uint(v));
}

// =================== fp16 GEMM: BM=128 BN=256, 512 thr =====================
// MODE: 0 = relu -> fp16 out (ld 2048)
//       1 = none -> f32 ml (ld 512) + fp16 mu (cols < 256, ld 256)
//       2 = relu -> fp16 out (ld 2048) + inline amax into g_scales[1]
template<int MODE>
__global__ void __launch_bounds__(512, 1)
gemm_mma(const __half* __restrict__ A, const __half* __restrict__ B,
         const float* __restrict__ bias,
         float* __restrict__ outf, __half* __restrict__ oh,
         unsigned* __restrict__ scales,
         int Kd, int ldA)
{
    extern __shared__ char smem[];
    const uint32_t sbase = smem_u32(smem);
    constexpr uint32_t STG = 49152;

    const int tid  = threadIdx.x;
    const int lane = tid & 31, wid = tid >> 5;
    const int wm = (wid >> 3) * 64;
    const int wn = (wid & 7) * 32;
    const int m0 = blockIdx.y * 128;
    const int n0 = blockIdx.x * 256;
    const int nk = Kd >> 6;

    const __half* Ag = A + (size_t)m0 * ldA;
    const __half* Bg = B + (size_t)n0 * Kd;

    auto load_stage = [&](int kc) {
        const uint32_t sA = sbase + (uint32_t)(kc % 3) * STG;
        const uint32_t sB = sA + 16384;
        const __half* ga = Ag + kc * 64;
        const __half* gb = Bg + kc * 64;
        #pragma unroll
        for (int i = 0; i < 2; i++) {
            const int u = tid + i * 512;
            const int row = u >> 3, c = u & 7;
            cp16(sA + SWZ128(row * 128 + c * 16), ga + (size_t)row * ldA + c * 8);
        }
        #pragma unroll
        for (int i = 0; i < 4; i++) {
            const int u = tid + i * 512;
            const int row = u >> 3, c = u & 7;
            cp16(sB + SWZ128(row * 128 + c * 16), gb + (size_t)row * Kd + c * 8);
        }
        asm volatile("cp.async.commit_group;" ::: "memory");
    };

    float acc[4][4][4];
    #pragma unroll
    for (int i = 0; i < 4; i++)
        #pragma unroll
        for (int j = 0; j < 4; j++)
            #pragma unroll
            for (int k = 0; k < 4; k++) acc[i][j][k] = 0.0f;

    load_stage(0);
    load_stage(1);

    const int r  = lane & 15;
    const int ch = lane >> 4;

    for (int kc = 0; kc < nk; kc++) {
        if (kc + 1 < nk) asm volatile("cp.async.wait_group 1;" ::: "memory");
        else             asm volatile("cp.async.wait_group 0;" ::: "memory");
        __syncthreads();
        const uint32_t sA = sbase + (uint32_t)(kc % 3) * STG;
        const uint32_t sB = sA + 16384;

        #pragma unroll
        for (int ks = 0; ks < 4; ks++) {
            const int c = ks * 2 + ch;
            uint32_t a[4][4], b[2][4];
            #pragma unroll
            for (int mi = 0; mi < 4; mi++)
                ldsm_x4(a[mi], sA + SWZ128((wm + mi * 16 + r) * 128 + c * 16));
            #pragma unroll
            for (int g = 0; g < 2; g++)
                ldsm_x4(b[g], sB + SWZ128((wn + g * 16 + r) * 128 + c * 16));
            #pragma unroll
            for (int mi = 0; mi < 4; mi++)
                #pragma unroll
                for (int ni = 0; ni < 4; ni++)
                    mma16816(acc[mi][ni], a[mi],
                             b[ni >> 1][ni & 1], b[ni >> 1][2 + (ni & 1)]);
        }
        if (kc + 2 < nk) load_stage(kc + 2);
    }

    const int row0 = lane >> 2;
    const int col0 = (lane & 3) * 2;
    float mx = 0.0f;
    #pragma unroll
    for (int mi = 0; mi < 4; mi++) {
        #pragma unroll
        for (int ni = 0; ni < 4; ni++) {
            const int gc = n0 + wn + ni * 8 + col0;
            const float b0 = __ldg(bias + gc);
            const float b1 = __ldg(bias + gc + 1);
            #pragma unroll
            for (int h = 0; h < 2; h++) {
                const int gr = m0 + wm + mi * 16 + row0 + h * 8;
                float v0 = acc[mi][ni][h * 2 + 0] + b0;
                float v1 = acc[mi][ni][h * 2 + 1] + b1;
                if (MODE == 0 || MODE == 2) {
                    v0 = fmaxf(v0, 0.0f); v1 = fmaxf(v1, 0.0f);
                    if (MODE == 2) mx = fmaxf(mx, fmaxf(v0, v1));
                    *reinterpret_cast<__half2*>(oh + (size_t)gr * 2048 + gc) =
                        __floats2half2_rn(v0, v1);
                } else {
                    outf[(size_t)gr * 512 + gc]     = v0;
                    outf[(size_t)gr * 512 + gc + 1] = v1;
                    if (gc < 256)
                        *reinterpret_cast<__half2*>(oh + (size_t)gr * 256 + gc) =
                            __floats2half2_rn(v0, v1);
                }
            }
        }
    }
    if (MODE == 2) atomic_amax(scales + 1, mx);
}

// ============== int8 GEMM (dec2): sigmoid + unpatchify scatter ==============
// A:[M,K] s8 (hd), B:[N,K] s8 (w4^T). BM=128, BN=256, BK=128 (bytes), 512 thr.
// logit = acc * (amaxA/127)*(amaxB/127) + bias.
__global__ void __launch_bounds__(512, 1)
gemm_i8(const int8_t* __restrict__ A, const int8_t* __restrict__ B,
        const float* __restrict__ bias, float* __restrict__ outf,
        const unsigned* __restrict__ scales, int Kd)
{
    extern __shared__ char smem[];
    const uint32_t sbase = smem_u32(smem);
    constexpr uint32_t STG = 49152;

    const int tid  = threadIdx.x;
    const int lane = tid & 31, wid = tid >> 5;
    const int wm = (wid >> 3) * 64;
    const int wn = (wid & 7) * 32;
    const int m0 = blockIdx.y * 128;
    const int n0 = blockIdx.x * 256;
    const int nk = Kd >> 7;                  // 128 int8 per tile-row

    const int8_t* Ag = A + (size_t)m0 * Kd;
    const int8_t* Bg = B + (size_t)n0 * Kd;

    auto load_stage = [&](int kc) {
        const uint32_t sA = sbase + (uint32_t)(kc % 3) * STG;
        const uint32_t sB = sA + 16384;
        const int8_t* ga = Ag + kc * 128;
        const int8_t* gb = Bg + kc * 128;
        #pragma unroll
        for (int i = 0; i < 2; i++) {
            const int u = tid + i * 512;
            const int row = u >> 3, c = u & 7;
            cp16(sA + SWZ128(row * 128 + c * 16), ga + (size_t)row * Kd + c * 16);
        }
        #pragma unroll
        for (int i = 0; i < 4; i++) {
            const int u = tid + i * 512;
            const int row = u >> 3, c = u & 7;
            cp16(sB + SWZ128(row * 128 + c * 16), gb + (size_t)row * Kd + c * 16);
        }
        asm volatile("cp.async.commit_group;" ::: "memory");
    };

    int acc[4][4][4];
    #pragma unroll
    for (int i = 0; i < 4; i++)
        #pragma unroll
        for (int j = 0; j < 4; j++)
            #pragma unroll
            for (int k = 0; k < 4; k++) acc[i][j][k] = 0;

    load_stage(0);
    load_stage(1);

    const int r  = lane & 15;
    const int ch = lane >> 4;

    for (int kc = 0; kc < nk; kc++) {
        if (kc + 1 < nk) asm volatile("cp.async.wait_group 1;" ::: "memory");
        else             asm volatile("cp.async.wait_group 0;" ::: "memory");
        __syncthreads();
        const uint32_t sA = sbase + (uint32_t)(kc % 3) * STG;
        const uint32_t sB = sA + 16384;

        #pragma unroll
        for (int ks = 0; ks < 4; ks++) {      // 4 x k32 per 128B row
            const int c = ks * 2 + ch;
            uint32_t a[4][4], b[2][4];
            #pragma unroll
            for (int mi = 0; mi < 4; mi++)
                ldsm_x4(a[mi], sA + SWZ128((wm + mi * 16 + r) * 128 + c * 16));
            #pragma unroll
            for (int g = 0; g < 2; g++)
                ldsm_x4(b[g], sB + SWZ128((wn + g * 16 + r) * 128 + c * 16));
            #pragma unroll
            for (int mi = 0; mi < 4; mi++)
                #pragma unroll
                for (int ni = 0; ni < 4; ni++)
                    mma16832s8(acc[mi][ni], a[mi],
                               b[ni >> 1][ni & 1], b[ni >> 1][2 + (ni & 1)]);
        }
        if (kc + 2 < nk) load_stage(kc + 2);
    }

    const float sAB = (__uint_as_float(scales[1]) / 127.0f) *
                      (__uint_as_float(scales[0]) / 127.0f);
    const int row0 = lane >> 2;
    const int col0 = (lane & 3) * 2;
    #pragma unroll
    for (int mi = 0; mi < 4; mi++) {
        #pragma unroll
        for (int ni = 0; ni < 4; ni++) {
            const int gc = n0 + wn + ni * 8 + col0;
            const float b0 = __ldg(bias + gc);
            const float b1 = __ldg(bias + gc + 1);
            #pragma unroll
            for (int h = 0; h < 2; h++) {
                const int gr = m0 + wm + mi * 16 + row0 + h * 8;
                float v0 = (float)acc[mi][ni][h * 2 + 0] * sAB + b0;
                float v1 = (float)acc[mi][ni][h * 2 + 1] * sAB + b1;
                v0 = 1.0f / (1.0f + __expf(-v0));
                v1 = 1.0f / (1.0f + __expf(-v1));
                const int b  = gr >> 6, g = gr & 63;
                const int gh = g >> 3, gw = g & 7;
                const int cc = gc >> 8, kh = (gc >> 4) & 15, kw = gc & 15;
                const size_t idx =
                    ((size_t)(b * 3 + cc) * 128 + gh * 16 + kh) * 128 + gw * 16 + kw;
                *reinterpret_cast<float2*>(outf + idx) = make_float2(v0, v1);
            }
        }
    }
}

// ------------------------------ prep kernels --------------------------------
__global__ void init_scales_kernel(unsigned* s) {
    if (threadIdx.x < 2) s[threadIdx.x] = 0u;
}

__global__ void amax_f32_kernel(const float* __restrict__ w, int n,
                                unsigned* __restrict__ slot)
{
    float mx = 0.0f;
    for (int i = blockIdx.x * blockDim.x + threadIdx.x; i < n;
         i += gridDim.x * blockDim.x)
        mx = fmaxf(mx, fabsf(w[i]));
    atomic_amax(slot, mx);
}

__global__ void patchify_kernel(const float* __restrict__ x,
                                __half* __restrict__ p, int n)
{
    int i = blockIdx.x * blockDim.x + threadIdx.x;
    if (i >= n) return;
    const int kw    = i & 15;
    const int kh    = (i >> 4) & 15;
    const int c     = (i >> 8) % 3;
    const int token = i / PD;
    const int gw = token & 7;
    const int gh = (token >> 3) & 7;
    const int b  = token >> 6;
    const size_t src = ((size_t)(b * 3 + c) * 128 + gh * 16 + kh) * 128 + gw * 16 + kw;
    p[i] = __float2half_rn(x[src]);
}

// t[n,k] = w[k,n]  fp32 -> fp16 transpose. blockDim (32,8).
__global__ void wT_kernel(const float* __restrict__ w, int Kd, int Nd,
                          __half* __restrict__ t)
{
    __shared__ float tile[32][33];
    const int x = blockIdx.x * 32 + threadIdx.x;
    const int y = blockIdx.y * 32 + threadIdx.y;
    #pragma unroll
    for (int i = 0; i < 32; i += 8)
        tile[threadIdx.y + i][threadIdx.x] = w[(size_t)(y + i) * Nd + x];
    __syncthreads();
    const int n = blockIdx.x * 32 + threadIdx.y;
    const int k = blockIdx.y * 32 + threadIdx.x;
    #pragma unroll
    for (int i = 0; i < 32; i += 8)
        t[(size_t)(n + i) * Kd + k] = __float2half_rn(tile[threadIdx.x][threadIdx.y + i]);
}

// t8[n,k] = quantize(w[k,n]) with per-tensor scale from slot.
__global__ void wT8_kernel(const float* __restrict__ w, int Kd, int Nd,
                           int8_t* __restrict__ t8,
                           const unsigned* __restrict__ slot)
{
    __shared__ float tile[32][33];
    const float s = 127.0f / __uint_as_float(*slot);
    const int x = blockIdx.x * 32 + threadIdx.x;
    const int y = blockIdx.y * 32 + threadIdx.y;
    #pragma unroll
    for (int i = 0; i < 32; i += 8)
        tile[threadIdx.y + i][threadIdx.x] = w[(size_t)(y + i) * Nd + x];
    __syncthreads();
    const int n = blockIdx.x * 32 + threadIdx.y;
    const int k = blockIdx.y * 32 + threadIdx.x;
    #pragma unroll
    for (int i = 0; i < 32; i += 8) {
        int q = __float2int_rn(tile[threadIdx.x][threadIdx.y + i] * s);
        q = max(-127, min(127, q));
        t8[(size_t)(n + i) * Kd + k] = (int8_t)q;
    }
}

// hd fp16 -> int8 with scale from slot (values >= 0 after relu).
__global__ void quant_hd_kernel(const __half* __restrict__ hd,
                                int8_t* __restrict__ hd8, int n,
                                const unsigned* __restrict__ slot)
{
    const float s = 127.0f / __uint_as_float(*slot);
    int i = blockIdx.x * blockDim.x + threadIdx.x;
    if (i >= n) return;
    const float2 v = __half22float2(*reinterpret_cast<const __half2*>(hd + 2 * i));
    char2 q;
    q.x = (char)min(127, __float2int_rn(v.x * s));
    q.y = (char)min(127, __float2int_rn(v.y * s));
    *reinterpret_cast<char2*>(hd8 + 2 * i) = q;
}

// out2[b, l, g] = ml[b*64+g, l]
__global__ void transpose_ml_tiled(const float* __restrict__ ml,
                                   float* __restrict__ out2)
{
    __shared__ float tile[32][33];
    const int b  = blockIdx.z;
    const int l0 = blockIdx.x * 32;
    const int g0 = blockIdx.y * 32;
    #pragma unroll
    for (int i = 0; i < 32; i += 8) {
        const int g = g0 + threadIdx.y + i;
        tile[threadIdx.y + i][threadIdx.x] =
            ml[(size_t)(b * 64 + g) * L2D + l0 + threadIdx.x];
    }
    __syncthreads();
    #pragma unroll
    for (int i = 0; i < 32; i += 8) {
        const int l = l0 + threadIdx.y + i;
        out2[(size_t)b * (L2D * 64) + (size_t)l * 64 + g0 + threadIdx.x] =
            tile[threadIdx.x][threadIdx.y + i];
    }
}

// ------------------------------- launcher -----------------------------------
extern "C" void kernel_launch(void* const* d_in, const int* in_sizes, int n_in,
                              void* d_out, int out_size)
{
    const float* x      = (const float*)d_in[0];
    const float* w_enc1 = (const float*)d_in[1];
    const float* b_enc1 = (const float*)d_in[2];
    const float* w_enc2 = (const float*)d_in[3];
    const float* b_enc2 = (const float*)d_in[4];
    const float* w_dec1 = (const float*)d_in[5];
    const float* b_dec1 = (const float*)d_in[6];
    const float* w_dec2 = (const float*)d_in[7];
    const float* b_dec2 = (const float*)d_in[8];

    __half *p, *he, *mu, *hd, *w1t, *w2t, *w3t;
    int8_t *hd8, *w4t8;
    float* ml;
    unsigned* scales;
    cudaGetSymbolAddress((void**)&p,     g_p);
    cudaGetSymbolAddress((void**)&he,    g_he);
    cudaGetSymbolAddress((void**)&ml,    g_ml);
    cudaGetSymbolAddress((void**)&mu,    g_mu);
    cudaGetSymbolAddress((void**)&hd,    g_hd);
    cudaGetSymbolAddress((void**)&hd8,   g_hd8);
    cudaGetSymbolAddress((void**)&w1t,   g_w1t);
    cudaGetSymbolAddress((void**)&w2t,   g_w2t);
    cudaGetSymbolAddress((void**)&w3t,   g_w3t);
    cudaGetSymbolAddress((void**)&w4t8,  g_w4t8);
    cudaGetSymbolAddress((void**)&scales, g_scales);

    float* out   = (float*)d_out;
    float* recon = out;
    float* ml2d  = out + (size_t)256 * 3 * 128 * 128;

    const int SMEM = 3 * 49152;   // 144 KB
    cudaFuncSetAttribute(gemm_mma<0>, cudaFuncAttributeMaxDynamicSharedMemorySize, SMEM);
    cudaFuncSetAttribute(gemm_mma<1>, cudaFuncAttributeMaxDynamicSharedMemorySize, SMEM);
    cudaFuncSetAttribute(gemm_mma<2>, cudaFuncAttributeMaxDynamicSharedMemorySize, SMEM);
    cudaFuncSetAttribute(gemm_i8,     cudaFuncAttributeMaxDynamicSharedMemorySize, SMEM);

    const int n_img = 256 * 3 * 128 * 128;

    // 0) zero amax slots (graph-replay deterministic)
    init_scales_kernel<<<1, 32>>>(scales);

    // 1) patchify -> fp16
    patchify_kernel<<<(n_img + 255) / 256, 256>>>(x, p, n_img);

    // 2) weight transposes; w_dec2 -> int8 (amax first)
    dim3 tb32(32, 8);
    wT_kernel<<<dim3(HD / 32,   PD / 32),   tb32>>>(w_enc1, PD,   HD,  w1t);
    wT_kernel<<<dim3(L2D / 32,  HD / 32),   tb32>>>(w_enc2, HD,   L2D, w2t);
    wT_kernel<<<dim3(HD / 32,   LDIM / 32), tb32>>>(w_dec1, LDIM, HD,  w3t);
    amax_f32_kernel<<<512, 256>>>(w_dec2, HD * PD, scales + 0);
    wT8_kernel<<<dim3(PD / 32, HD / 32), tb32>>>(w_dec2, HD, PD, w4t8, scales + 0);

    // 3) enc1: he = relu(p @ w1 + b1)     [16384,768] x [768,2048]
    gemm_mma<0><<<dim3(HD / 256, TOK / 128), 512, SMEM>>>(
        p, w1t, b_enc1, nullptr, he, scales, PD, PD);

    // 4) enc2: ml = he @ w2 + b2          [16384,2048] x [2048,512]
    gemm_mma<1><<<dim3(L2D / 256, TOK / 128), 512, SMEM>>>(
        he, w2t, b_enc2, ml, mu, scales, HD, HD);

    // 5) mu_logvar_2d output
    transpose_ml_tiled<<<dim3(L2D / 32, 2, 256), tb32>>>(ml, ml2d);

    // 6) dec1: hd = relu(mu @ w3 + b3), inline amax(hd) -> scales[1]
    gemm_mma<2><<<dim3(HD / 256, TOK / 128), 512, SMEM>>>(
        mu, w3t, b_dec1, nullptr, hd, scales, LDIM, LDIM);

    // 7) quantize hd -> int8
    quant_hd_kernel<<<(TOK * HD / 2 + 255) / 256, 256>>>(hd, hd8, TOK * HD / 2, scales + 1);

    // 8) dec2 (int8 IMMA): recon = sigmoid(hd8 @ w4t8 * s + b4), fused scatter
    gemm_i8<<<dim3(PD / 256, TOK / 128), 512, SMEM>>>(
        hd8, w4t8, b_dec2, recon, scales, HD);
}

// round 13
// speedup vs baseline: 1.5550x; 1.5550x over previous
#include <cuda_runtime.h>
#include <cuda_fp16.h>
#include <cstdint>
#include <cstddef>

// ---------------------------------------------------------------------------
// ConvVAE2d via mma.sync fp16 GEMMs (baseline sm_103 PTX: cp.async + ldmatrix
// + mma.sync.m16n8k16). Legacy pipe rate rt=16/SMSP is the floor (R9/R11/R12
// probes: f16-acc same rate, int8 4x slower). R13: overhead removal —
// single merged prep kernel; enc2 epilogue writes mu_logvar_2d directly
// (smem-staged transpose), eliminating the ml buffer + transpose kernel.
// ---------------------------------------------------------------------------

#define TOK 16384
#define PD  768
#define HD  2048
#define L2D 512
#define LDIM 256

// ----------------------------- scratch -------------------------------------
__device__ __align__(256) __half g_p[TOK * PD];
__device__ __align__(256) __half g_he[TOK * HD];
__device__ __align__(256) __half g_mu[TOK * LDIM];
__device__ __align__(256) __half g_hd[TOK * HD];
__device__ __align__(256) __half g_w1t[HD * PD];
__device__ __align__(256) __half g_w2t[L2D * HD];
__device__ __align__(256) __half g_w3t[HD * LDIM];
__device__ __align__(256) __half g_w4t[PD * HD];

// ----------------------------- helpers -------------------------------------
__device__ __forceinline__ uint32_t smem_u32(const void* p) {
    uint32_t a;
    asm("{ .reg .u64 t; cvta.to.shared.u64 t, %1; cvt.u32.u64 %0, t; }"
        : "=r"(a) : "l"(p));
    return a;
}

#define SWZ128(o) ((uint32_t)(o) ^ ((((uint32_t)(o)) >> 3) & 0x70u))

__device__ __forceinline__ void cp16(uint32_t dst, const void* src) {
    asm volatile("cp.async.cg.shared.global [%0], [%1], 16;"
                 :: "r"(dst), "l"(src) : "memory");
}
__device__ __forceinline__ void ldsm_x4(uint32_t* r, uint32_t addr) {
    asm volatile("ldmatrix.sync.aligned.m8n8.x4.shared.b16 {%0,%1,%2,%3}, [%4];"
                 : "=r"(r[0]), "=r"(r[1]), "=r"(r[2]), "=r"(r[3]) : "r"(addr));
}
__device__ __forceinline__ void mma16816(float* c, const uint32_t* a,
                                         uint32_t b0, uint32_t b1) {
    asm volatile(
        "mma.sync.aligned.m16n8k16.row.col.f32.f16.f16.f32 "
        "{%0,%1,%2,%3}, {%4,%5,%6,%7}, {%8,%9}, {%0,%1,%2,%3};"
        : "+f"(c[0]), "+f"(c[1]), "+f"(c[2]), "+f"(c[3])
        : "r"(a[0]), "r"(a[1]), "r"(a[2]), "r"(a[3]), "r"(b0), "r"(b1));
}

// ------------------------------- GEMM kernel --------------------------------
// C[M,N] = act(A[M,K] @ B^T + bias).  A:[M,K] fp16 K-contig. B:[N,K] fp16
// (= W^T) K-contig.  BM=128, BN=256, BK=64, 512 thr, 16 warps (2M x 8N),
// warp tile 64x32, 3-stage cp.async pipeline, SW128 smem.
// MODE: 0 = relu -> fp16 out (ld 2048)
//       1 = enc2: fp16 mu (cols<256) + smem-transposed f32 ml2d[b, l, g]
//       3 = sigmoid -> fused unpatchify scatter to recon (f32)
template<int MODE>
__global__ void __launch_bounds__(512, 1)
gemm_mma(const __half* __restrict__ A, const __half* __restrict__ B,
         const float* __restrict__ bias,
         float* __restrict__ outf, __half* __restrict__ oh,
         int Kd, int ldA)
{
    extern __shared__ char smem[];
    const uint32_t sbase = smem_u32(smem);
    constexpr uint32_t STG = 49152;         // 16KB A + 32KB B per stage

    const int tid  = threadIdx.x;
    const int lane = tid & 31, wid = tid >> 5;
    const int wm = (wid >> 3) * 64;         // warp M offset (0/64)
    const int wn = (wid & 7) * 32;          // warp N offset (0..224)
    const int m0 = blockIdx.y * 128;
    const int n0 = blockIdx.x * 256;
    const int nk = Kd >> 6;

    const __half* Ag = A + (size_t)m0 * ldA;
    const __half* Bg = B + (size_t)n0 * Kd;

    auto load_stage = [&](int kc) {
        const uint32_t sA = sbase + (uint32_t)(kc % 3) * STG;
        const uint32_t sB = sA + 16384;
        const __half* ga = Ag + kc * 64;
        const __half* gb = Bg + kc * 64;
        #pragma unroll
        for (int i = 0; i < 2; i++) {           // A: 128 rows x 128B
            const int u = tid + i * 512;
            const int row = u >> 3, c = u & 7;
            cp16(sA + SWZ128(row * 128 + c * 16), ga + (size_t)row * ldA + c * 8);
        }
        #pragma unroll
        for (int i = 0; i < 4; i++) {           // B: 256 rows x 128B
            const int u = tid + i * 512;
            const int row = u >> 3, c = u & 7;
            cp16(sB + SWZ128(row * 128 + c * 16), gb + (size_t)row * Kd + c * 8);
        }
        asm volatile("cp.async.commit_group;" ::: "memory");
    };

    float acc[4][4][4];
    #pragma unroll
    for (int i = 0; i < 4; i++)
        #pragma unroll
        for (int j = 0; j < 4; j++)
            #pragma unroll
            for (int k = 0; k < 4; k++) acc[i][j][k] = 0.0f;

    load_stage(0);
    load_stage(1);

    const int r  = lane & 15;
    const int ch = lane >> 4;

    for (int kc = 0; kc < nk; kc++) {
        if (kc + 1 < nk) asm volatile("cp.async.wait_group 1;" ::: "memory");
        else             asm volatile("cp.async.wait_group 0;" ::: "memory");
        __syncthreads();
        const uint32_t sA = sbase + (uint32_t)(kc % 3) * STG;
        const uint32_t sB = sA + 16384;

        #pragma unroll
        for (int ks = 0; ks < 4; ks++) {        // 4 x k16 per BK=64
            const int c = ks * 2 + ch;          // 16B chunk index
            uint32_t a[4][4], b[2][4];
            #pragma unroll
            for (int mi = 0; mi < 4; mi++)
                ldsm_x4(a[mi], sA + SWZ128((wm + mi * 16 + r) * 128 + c * 16));
            #pragma unroll
            for (int g = 0; g < 2; g++)
                ldsm_x4(b[g], sB + SWZ128((wn + g * 16 + r) * 128 + c * 16));
            #pragma unroll
            for (int mi = 0; mi < 4; mi++)
                #pragma unroll
                for (int ni = 0; ni < 4; ni++)
                    mma16816(acc[mi][ni], a[mi],
                             b[ni >> 1][ni & 1], b[ni >> 1][2 + (ni & 1)]);
        }
        if (kc + 2 < nk) load_stage(kc + 2);
    }

    // ------------------------------ epilogue --------------------------------
    const int row0 = lane >> 2;
    const int col0 = (lane & 3) * 2;

    if (MODE == 1) {
        // enc2: stage tile [col][row] in smem (stride 132 -> conflict-free),
        // write mu fp16 inline; then warp-cooperative coalesced ml2d stores.
        __syncthreads();                        // tiles dead; reuse smem
        float* stg = reinterpret_cast<float*>(smem);
        #pragma unroll
        for (int mi = 0; mi < 4; mi++) {
            #pragma unroll
            for (int ni = 0; ni < 4; ni++) {
                const int lc = wn + ni * 8 + col0;        // local col 0..255
                const float b0 = __ldg(bias + n0 + lc);
                const float b1 = __ldg(bias + n0 + lc + 1);
                #pragma unroll
                for (int h = 0; h < 2; h++) {
                    const int lr = wm + mi * 16 + row0 + h * 8;  // local row
                    const float v0 = acc[mi][ni][h * 2 + 0] + b0;
                    const float v1 = acc[mi][ni][h * 2 + 1] + b1;
                    stg[(lc) * 132 + lr]     = v0;
                    stg[(lc + 1) * 132 + lr] = v1;
                    if (n0 == 0) {           // mu = cols < 256 (tile n0==0)
                        *reinterpret_cast<__half2*>(
                            oh + (size_t)(m0 + lr) * 256 + lc) =
                            __floats2half2_rn(v0, v1);
                    }
                }
            }
        }
        __syncthreads();
        // 512 output rows: (l in 0..255) x (bh in 0..1); one warp per row.
        const int b0i = m0 >> 6;
        for (int rr = 0; rr < 32; rr++) {
            const int rowid = wid * 32 + rr;          // 0..511
            const int l  = rowid >> 1;
            const int bh = rowid & 1;
            const float2 v = *reinterpret_cast<const float2*>(
                &stg[l * 132 + bh * 64 + lane * 2]);
            *reinterpret_cast<float2*>(
                outf + (size_t)(b0i + bh) * (L2D * 64) +
                       (size_t)(n0 + l) * 64 + lane * 2) = v;
        }
        return;
    }

    #pragma unroll
    for (int mi = 0; mi < 4; mi++) {
        #pragma unroll
        for (int ni = 0; ni < 4; ni++) {
            const int gc = n0 + wn + ni * 8 + col0;
            const float b0 = __ldg(bias + gc);
            const float b1 = __ldg(bias + gc + 1);
            #pragma unroll
            for (int h = 0; h < 2; h++) {
                const int gr = m0 + wm + mi * 16 + row0 + h * 8;
                float v0 = acc[mi][ni][h * 2 + 0] + b0;
                float v1 = acc[mi][ni][h * 2 + 1] + b1;
                if (MODE == 0) {
                    v0 = fmaxf(v0, 0.0f); v1 = fmaxf(v1, 0.0f);
                    *reinterpret_cast<__half2*>(oh + (size_t)gr * 2048 + gc) =
                        __floats2half2_rn(v0, v1);
                } else {
                    v0 = 1.0f / (1.0f + __expf(-v0));
                    v1 = 1.0f / (1.0f + __expf(-v1));
                    // fused unpatchify: gr = token, gc = c*256 + kh*16 + kw
                    const int b  = gr >> 6, g = gr & 63;
                    const int gh = g >> 3, gw = g & 7;
                    const int cc = gc >> 8, kh = (gc >> 4) & 15, kw = gc & 15;
                    const size_t idx =
                        ((size_t)(b * 3 + cc) * 128 + gh * 16 + kh) * 128 + gw * 16 + kw;
                    *reinterpret_cast<float2*>(outf + idx) = make_float2(v0, v1);
                }
            }
        }
    }
}

// --------------------- merged prep kernel (1 launch) ------------------------
// blocks [0, 49152): patchify fp32->fp16
// then 4 weight transposes (32x32 smem tiles), block ranges per weight.
#define PREP_PATCH 49152
#define PREP_W1    (PREP_PATCH + 1536)   // w1: gx=64, gy=24
#define PREP_W2    (PREP_W1 + 1024)      // w2: gx=16, gy=64
#define PREP_W3    (PREP_W2 + 512)       // w3: gx=64, gy=8
#define PREP_TOTAL (PREP_W3 + 1536)      // w4: gx=24, gy=64

__global__ void __launch_bounds__(256)
prep_kernel(const float* __restrict__ x, __half* __restrict__ p,
            const float* __restrict__ w1, __half* __restrict__ w1t,
            const float* __restrict__ w2, __half* __restrict__ w2t,
            const float* __restrict__ w3, __half* __restrict__ w3t,
            const float* __restrict__ w4, __half* __restrict__ w4t)
{
    __shared__ float tile[32][33];
    int bid = blockIdx.x;
    const int tid = threadIdx.x;

    if (bid < PREP_PATCH) {
        const int i = bid * 256 + tid;
        const int kw    = i & 15;
        const int kh    = (i >> 4) & 15;
        const int c     = (i >> 8) % 3;
        const int token = i / PD;
        const int gw = token & 7;
        const int gh = (token >> 3) & 7;
        const int b  = token >> 6;
        const size_t src =
            ((size_t)(b * 3 + c) * 128 + gh * 16 + kh) * 128 + gw * 16 + kw;
        p[i] = __float2half_rn(x[src]);
        return;
    }

    const float* w; __half* t; int Kd, Nd, gx;
    if (bid < PREP_W1)      { bid -= PREP_PATCH; w = w1; t = w1t; Kd = PD;   Nd = HD;  gx = 64; }
    else if (bid < PREP_W2) { bid -= PREP_W1;    w = w2; t = w2t; Kd = HD;   Nd = L2D; gx = 16; }
    else if (bid < PREP_W3) { bid -= PREP_W2;    w = w3; t = w3t; Kd = LDIM; Nd = HD;  gx = 64; }
    else                    { bid -= PREP_W3;    w = w4; t = w4t; Kd = HD;   Nd = PD;  gx = 24; }

    const int bx = bid % gx, by = bid / gx;
    const int tx = tid & 31, ty = tid >> 5;

    const int xx = bx * 32 + tx;     // n
    const int yy = by * 32 + ty;     // k
    #pragma unroll
    for (int i = 0; i < 32; i += 8)
        tile[ty + i][tx] = w[(size_t)(yy + i) * Nd + xx];
    __syncthreads();
    const int n = bx * 32 + ty;
    const int k = by * 32 + tx;
    #pragma unroll
    for (int i = 0; i < 32; i += 8)
        t[(size_t)(n + i) * Kd + k] = __float2half_rn(tile[tx][ty + i]);
}

// ------------------------------- launcher -----------------------------------
extern "C" void kernel_launch(void* const* d_in, const int* in_sizes, int n_in,
                              void* d_out, int out_size)
{
    const float* x      = (const float*)d_in[0];
    const float* w_enc1 = (const float*)d_in[1];
    const float* b_enc1 = (const float*)d_in[2];
    const float* w_enc2 = (const float*)d_in[3];
    const float* b_enc2 = (const float*)d_in[4];
    const float* w_dec1 = (const float*)d_in[5];
    const float* b_dec1 = (const float*)d_in[6];
    const float* w_dec2 = (const float*)d_in[7];
    const float* b_dec2 = (const float*)d_in[8];

    __half *p, *he, *mu, *hd, *w1t, *w2t, *w3t, *w4t;
    cudaGetSymbolAddress((void**)&p,   g_p);
    cudaGetSymbolAddress((void**)&he,  g_he);
    cudaGetSymbolAddress((void**)&mu,  g_mu);
    cudaGetSymbolAddress((void**)&hd,  g_hd);
    cudaGetSymbolAddress((void**)&w1t, g_w1t);
    cudaGetSymbolAddress((void**)&w2t, g_w2t);
    cudaGetSymbolAddress((void**)&w3t, g_w3t);
    cudaGetSymbolAddress((void**)&w4t, g_w4t);

    float* out   = (float*)d_out;
    float* recon = out;
    float* ml2d  = out + (size_t)256 * 3 * 128 * 128;

    const int SMEM = 3 * 49152;   // 144 KB (>= 256*132*4 = 132 KB staging)
    cudaFuncSetAttribute(gemm_mma<0>, cudaFuncAttributeMaxDynamicSharedMemorySize, SMEM);
    cudaFuncSetAttribute(gemm_mma<1>, cudaFuncAttributeMaxDynamicSharedMemorySize, SMEM);
    cudaFuncSetAttribute(gemm_mma<3>, cudaFuncAttributeMaxDynamicSharedMemorySize, SMEM);

    // 1) merged prep: patchify + all 4 weight transposes
    prep_kernel<<<PREP_TOTAL, 256>>>(x, p, w_enc1, w1t, w_enc2, w2t,
                                     w_dec1, w3t, w_dec2, w4t);

    // 2) enc1: he = relu(p @ w1 + b1)     [16384,768] x [768,2048]
    gemm_mma<0><<<dim3(HD / 256, TOK / 128), 512, SMEM>>>(
        p, w1t, b_enc1, nullptr, he, PD, PD);

    // 3) enc2: mu_logvar -> ml2d (fused transpose) + mu fp16
    gemm_mma<1><<<dim3(L2D / 256, TOK / 128), 512, SMEM>>>(
        he, w2t, b_enc2, ml2d, mu, HD, HD);

    // 4) dec1: hd = relu(mu @ w3 + b3)    [16384,256] x [256,2048]
    gemm_mma<0><<<dim3(HD / 256, TOK / 128), 512, SMEM>>>(
        mu, w3t, b_dec1, nullptr, hd, LDIM, LDIM);

    // 5) dec2: recon = sigmoid(hd @ w4 + b4), fused unpatchify scatter
    gemm_mma<3><<<dim3(PD / 256, TOK / 128), 512, SMEM>>>(
        hd, w4t, b_dec2, recon, nullptr, HD, HD);
}

// round 14
// speedup vs baseline: 1.6593x; 1.0670x over previous
#include <cuda_runtime.h>
#include <cuda_fp16.h>
#include <cstdint>
#include <cstddef>

// ---------------------------------------------------------------------------
// ConvVAE2d via mma.sync fp16 GEMMs (baseline sm_103 PTX).
// R14: 2 CTAs/SM co-residency. R13 ncu showed tensor pipe only 39.6% active
// (latency/bubble-bound, NOT pipe-bound). 256 thr/CTA, BM=128 BN=128,
// warp grid 4Mx2N (warp tile 32x64), 3-stage cp.async, 96KB smem/CTA
// -> two CTAs interleave per SM: prologue/sync/epilogue bubbles overlap.
// ---------------------------------------------------------------------------

#define TOK 16384
#define PD  768
#define HD  2048
#define L2D 512
#define LDIM 256

// ----------------------------- scratch -------------------------------------
__device__ __align__(256) __half g_p[TOK * PD];
__device__ __align__(256) __half g_he[TOK * HD];
__device__ __align__(256) __half g_mu[TOK * LDIM];
__device__ __align__(256) __half g_hd[TOK * HD];
__device__ __align__(256) __half g_w1t[HD * PD];
__device__ __align__(256) __half g_w2t[L2D * HD];
__device__ __align__(256) __half g_w3t[HD * LDIM];
__device__ __align__(256) __half g_w4t[PD * HD];

// ----------------------------- helpers -------------------------------------
__device__ __forceinline__ uint32_t smem_u32(const void* p) {
    uint32_t a;
    asm("{ .reg .u64 t; cvta.to.shared.u64 t, %1; cvt.u32.u64 %0, t; }"
        : "=r"(a) : "l"(p));
    return a;
}

#define SWZ128(o) ((uint32_t)(o) ^ ((((uint32_t)(o)) >> 3) & 0x70u))

__device__ __forceinline__ void cp16(uint32_t dst, const void* src) {
    asm volatile("cp.async.cg.shared.global [%0], [%1], 16;"
                 :: "r"(dst), "l"(src) : "memory");
}
__device__ __forceinline__ void ldsm_x4(uint32_t* r, uint32_t addr) {
    asm volatile("ldmatrix.sync.aligned.m8n8.x4.shared.b16 {%0,%1,%2,%3}, [%4];"
                 : "=r"(r[0]), "=r"(r[1]), "=r"(r[2]), "=r"(r[3]) : "r"(addr));
}
__device__ __forceinline__ void mma16816(float* c, const uint32_t* a,
                                         uint32_t b0, uint32_t b1) {
    asm volatile(
        "mma.sync.aligned.m16n8k16.row.col.f32.f16.f16.f32 "
        "{%0,%1,%2,%3}, {%4,%5,%6,%7}, {%8,%9}, {%0,%1,%2,%3};"
        : "+f"(c[0]), "+f"(c[1]), "+f"(c[2]), "+f"(c[3])
        : "r"(a[0]), "r"(a[1]), "r"(a[2]), "r"(a[3]), "r"(b0), "r"(b1));
}

// ------------------------------- GEMM kernel --------------------------------
// C[M,N] = act(A[M,K] @ B^T + bias).  A:[M,K] fp16 K-contig. B:[N,K] fp16
// (= W^T) K-contig.  BM=128, BN=128, BK=64, 256 thr, 8 warps (4M x 2N),
// warp tile 32x64, 3-stage cp.async, SW128 smem, 2 CTAs/SM.
// MODE: 0 = relu -> fp16 out (ld 2048)
//       1 = enc2: fp16 mu (cols<256) + smem-transposed f32 ml2d[b, l, g]
//       3 = sigmoid -> fused unpatchify scatter to recon (f32)
template<int MODE>
__global__ void __launch_bounds__(256, 2)
gemm_mma(const __half* __restrict__ A, const __half* __restrict__ B,
         const float* __restrict__ bias,
         float* __restrict__ outf, __half* __restrict__ oh,
         int Kd, int ldA)
{
    extern __shared__ char smem[];
    const uint32_t sbase = smem_u32(smem);
    constexpr uint32_t STG = 32768;         // 16KB A + 16KB B per stage

    const int tid  = threadIdx.x;
    const int lane = tid & 31, wid = tid >> 5;
    const int wm = (wid >> 1) * 32;         // warp M offset (0..96)
    const int wn = (wid & 1) * 64;          // warp N offset (0/64)
    const int m0 = blockIdx.y * 128;
    const int n0 = blockIdx.x * 128;
    const int nk = Kd >> 6;

    const __half* Ag = A + (size_t)m0 * ldA;
    const __half* Bg = B + (size_t)n0 * Kd;

    auto load_stage = [&](int kc) {
        const uint32_t sA = sbase + (uint32_t)(kc % 3) * STG;
        const uint32_t sB = sA + 16384;
        const __half* ga = Ag + kc * 64;
        const __half* gb = Bg + kc * 64;
        #pragma unroll
        for (int i = 0; i < 4; i++) {           // A: 128 rows x 128B
            const int u = tid + i * 256;
            const int row = u >> 3, c = u & 7;
            cp16(sA + SWZ128(row * 128 + c * 16), ga + (size_t)row * ldA + c * 8);
        }
        #pragma unroll
        for (int i = 0; i < 4; i++) {           // B: 128 rows x 128B
            const int u = tid + i * 256;
            const int row = u >> 3, c = u & 7;
            cp16(sB + SWZ128(row * 128 + c * 16), gb + (size_t)row * Kd + c * 8);
        }
        asm volatile("cp.async.commit_group;" ::: "memory");
    };

    float acc[2][8][4];
    #pragma unroll
    for (int i = 0; i < 2; i++)
        #pragma unroll
        for (int j = 0; j < 8; j++)
            #pragma unroll
            for (int k = 0; k < 4; k++) acc[i][j][k] = 0.0f;

    load_stage(0);
    load_stage(1);

    const int r  = lane & 15;
    const int ch = lane >> 4;

    for (int kc = 0; kc < nk; kc++) {
        if (kc + 1 < nk) asm volatile("cp.async.wait_group 1;" ::: "memory");
        else             asm volatile("cp.async.wait_group 0;" ::: "memory");
        __syncthreads();
        const uint32_t sA = sbase + (uint32_t)(kc % 3) * STG;
        const uint32_t sB = sA + 16384;

        #pragma unroll
        for (int ks = 0; ks < 4; ks++) {        // 4 x k16 per BK=64
            const int c = ks * 2 + ch;          // 16B chunk index
            uint32_t a[2][4], b[4][4];
            #pragma unroll
            for (int mi = 0; mi < 2; mi++)
                ldsm_x4(a[mi], sA + SWZ128((wm + mi * 16 + r) * 128 + c * 16));
            #pragma unroll
            for (int g = 0; g < 4; g++)
                ldsm_x4(b[g], sB + SWZ128((wn + g * 16 + r) * 128 + c * 16));
            #pragma unroll
            for (int mi = 0; mi < 2; mi++)
                #pragma unroll
                for (int ni = 0; ni < 8; ni++)
                    mma16816(acc[mi][ni], a[mi],
                             b[ni >> 1][ni & 1], b[ni >> 1][2 + (ni & 1)]);
        }
        if (kc + 2 < nk) load_stage(kc + 2);
    }

    // ------------------------------ epilogue --------------------------------
    const int row0 = lane >> 2;
    const int col0 = (lane & 3) * 2;

    if (MODE == 1) {
        // enc2: stage tile [col][row] in smem (stride 132 -> conflict-free),
        // write mu fp16 inline (cols<256 i.e. n0<256); then coalesced ml2d.
        __syncthreads();                        // tiles dead; reuse smem
        float* stg = reinterpret_cast<float*>(smem);
        #pragma unroll
        for (int mi = 0; mi < 2; mi++) {
            #pragma unroll
            for (int ni = 0; ni < 8; ni++) {
                const int lc = wn + ni * 8 + col0;        // local col 0..127
                const float b0 = __ldg(bias + n0 + lc);
                const float b1 = __ldg(bias + n0 + lc + 1);
                #pragma unroll
                for (int h = 0; h < 2; h++) {
                    const int lr = wm + mi * 16 + row0 + h * 8;  // local row
                    const float v0 = acc[mi][ni][h * 2 + 0] + b0;
                    const float v1 = acc[mi][ni][h * 2 + 1] + b1;
                    stg[(lc) * 132 + lr]     = v0;
                    stg[(lc + 1) * 132 + lr] = v1;
                    if (n0 < 256) {          // mu = cols < 256
                        *reinterpret_cast<__half2*>(
                            oh + (size_t)(m0 + lr) * 256 + n0 + lc) =
                            __floats2half2_rn(v0, v1);
                    }
                }
            }
        }
        __syncthreads();
        // 256 output rows: (l in 0..127) x (bh in 0..1); one warp per row.
        const int b0i = m0 >> 6;
        #pragma unroll 4
        for (int rr = 0; rr < 32; rr++) {
            const int rowid = wid * 32 + rr;          // 0..255
            const int l  = rowid >> 1;
            const int bh = rowid & 1;
            const float2 v = *reinterpret_cast<const float2*>(
                &stg[l * 132 + bh * 64 + lane * 2]);
            *reinterpret_cast<float2*>(
                outf + (size_t)(b0i + bh) * (L2D * 64) +
                       (size_t)(n0 + l) * 64 + lane * 2) = v;
        }
        return;
    }

    #pragma unroll
    for (int mi = 0; mi < 2; mi++) {
        #pragma unroll
        for (int ni = 0; ni < 8; ni++) {
            const int gc = n0 + wn + ni * 8 + col0;
            const float b0 = __ldg(bias + gc);
            const float b1 = __ldg(bias + gc + 1);
            #pragma unroll
            for (int h = 0; h < 2; h++) {
                const int gr = m0 + wm + mi * 16 + row0 + h * 8;
                float v0 = acc[mi][ni][h * 2 + 0] + b0;
                float v1 = acc[mi][ni][h * 2 + 1] + b1;
                if (MODE == 0) {
                    v0 = fmaxf(v0, 0.0f); v1 = fmaxf(v1, 0.0f);
                    *reinterpret_cast<__half2*>(oh + (size_t)gr * 2048 + gc) =
                        __floats2half2_rn(v0, v1);
                } else {
                    v0 = 1.0f / (1.0f + __expf(-v0));
                    v1 = 1.0f / (1.0f + __expf(-v1));
                    // fused unpatchify: gr = token, gc = c*256 + kh*16 + kw
                    const int b  = gr >> 6, g = gr & 63;
                    const int gh = g >> 3, gw = g & 7;
                    const int cc = gc >> 8, kh = (gc >> 4) & 15, kw = gc & 15;
                    const size_t idx =
                        ((size_t)(b * 3 + cc) * 128 + gh * 16 + kh) * 128 + gw * 16 + kw;
                    *reinterpret_cast<float2*>(outf + idx) = make_float2(v0, v1);
                }
            }
        }
    }
}

// --------------------- merged prep kernel (1 launch) ------------------------
#define PREP_PATCH 49152
#define PREP_W1    (PREP_PATCH + 1536)   // w1: gx=64, gy=24
#define PREP_W2    (PREP_W1 + 1024)      // w2: gx=16, gy=64
#define PREP_W3    (PREP_W2 + 512)       // w3: gx=64, gy=8
#define PREP_TOTAL (PREP_W3 + 1536)      // w4: gx=24, gy=64

__global__ void __launch_bounds__(256)
prep_kernel(const float* __restrict__ x, __half* __restrict__ p,
            const float* __restrict__ w1, __half* __restrict__ w1t,
            const float* __restrict__ w2, __half* __restrict__ w2t,
            const float* __restrict__ w3, __half* __restrict__ w3t,
            const float* __restrict__ w4, __half* __restrict__ w4t)
{
    __shared__ float tile[32][33];
    int bid = blockIdx.x;
    const int tid = threadIdx.x;

    if (bid < PREP_PATCH) {
        const int i = bid * 256 + tid;
        const int kw    = i & 15;
        const int kh    = (i >> 4) & 15;
        const int c     = (i >> 8) % 3;
        const int token = i / PD;
        const int gw = token & 7;
        const int gh = (token >> 3) & 7;
        const int b  = token >> 6;
        const size_t src =
            ((size_t)(b * 3 + c) * 128 + gh * 16 + kh) * 128 + gw * 16 + kw;
        p[i] = __float2half_rn(x[src]);
        return;
    }

    const float* w; __half* t; int Kd, Nd, gx;
    if (bid < PREP_W1)      { bid -= PREP_PATCH; w = w1; t = w1t; Kd = PD;   Nd = HD;  gx = 64; }
    else if (bid < PREP_W2) { bid -= PREP_W1;    w = w2; t = w2t; Kd = HD;   Nd = L2D; gx = 16; }
    else if (bid < PREP_W3) { bid -= PREP_W2;    w = w3; t = w3t; Kd = LDIM; Nd = HD;  gx = 64; }
    else                    { bid -= PREP_W3;    w = w4; t = w4t; Kd = HD;   Nd = PD;  gx = 24; }

    const int bx = bid % gx, by = bid / gx;
    const int tx = tid & 31, ty = tid >> 5;

    const int xx = bx * 32 + tx;     // n
    const int yy = by * 32 + ty;     // k
    #pragma unroll
    for (int i = 0; i < 32; i += 8)
        tile[ty + i][tx] = w[(size_t)(yy + i) * Nd + xx];
    __syncthreads();
    const int n = bx * 32 + ty;
    const int k = by * 32 + tx;
    #pragma unroll
    for (int i = 0; i < 32; i += 8)
        t[(size_t)(n + i) * Kd + k] = __float2half_rn(tile[tx][ty + i]);
}

// ------------------------------- launcher -----------------------------------
extern "C" void kernel_launch(void* const* d_in, const int* in_sizes, int n_in,
                              void* d_out, int out_size)
{
    const float* x      = (const float*)d_in[0];
    const float* w_enc1 = (const float*)d_in[1];
    const float* b_enc1 = (const float*)d_in[2];
    const float* w_enc2 = (const float*)d_in[3];
    const float* b_enc2 = (const float*)d_in[4];
    const float* w_dec1 = (const float*)d_in[5];
    const float* b_dec1 = (const float*)d_in[6];
    const float* w_dec2 = (const float*)d_in[7];
    const float* b_dec2 = (const float*)d_in[8];

    __half *p, *he, *mu, *hd, *w1t, *w2t, *w3t, *w4t;
    cudaGetSymbolAddress((void**)&p,   g_p);
    cudaGetSymbolAddress((void**)&he,  g_he);
    cudaGetSymbolAddress((void**)&mu,  g_mu);
    cudaGetSymbolAddress((void**)&hd,  g_hd);
    cudaGetSymbolAddress((void**)&w1t, g_w1t);
    cudaGetSymbolAddress((void**)&w2t, g_w2t);
    cudaGetSymbolAddress((void**)&w3t, g_w3t);
    cudaGetSymbolAddress((void**)&w4t, g_w4t);

    float* out   = (float*)d_out;
    float* recon = out;
    float* ml2d  = out + (size_t)256 * 3 * 128 * 128;

    const int SMEM = 3 * 32768;   // 96 KB/CTA -> 2 CTAs/SM (192 KB)
    cudaFuncSetAttribute(gemm_mma<0>, cudaFuncAttributeMaxDynamicSharedMemorySize, SMEM);
    cudaFuncSetAttribute(gemm_mma<1>, cudaFuncAttributeMaxDynamicSharedMemorySize, SMEM);
    cudaFuncSetAttribute(gemm_mma<3>, cudaFuncAttributeMaxDynamicSharedMemorySize, SMEM);

    // 1) merged prep: patchify + all 4 weight transposes
    prep_kernel<<<PREP_TOTAL, 256>>>(x, p, w_enc1, w1t, w_enc2, w2t,
                                     w_dec1, w3t, w_dec2, w4t);

    // 2) enc1: he = relu(p @ w1 + b1)     [16384,768] x [768,2048]
    gemm_mma<0><<<dim3(HD / 128, TOK / 128), 256, SMEM>>>(
        p, w1t, b_enc1, nullptr, he, PD, PD);

    // 3) enc2: mu_logvar -> ml2d (fused transpose) + mu fp16
    gemm_mma<1><<<dim3(L2D / 128, TOK / 128), 256, SMEM>>>(
        he, w2t, b_enc2, ml2d, mu, HD, HD);

    // 4) dec1: hd = relu(mu @ w3 + b3)    [16384,256] x [256,2048]
    gemm_mma<0><<<dim3(HD / 128, TOK / 128), 256, SMEM>>>(
        mu, w3t, b_dec1, nullptr, hd, LDIM, LDIM);

    // 5) dec2: recon = sigmoid(hd @ w4 + b4), fused unpatchify scatter
    gemm_mma<3><<<dim3(PD / 128, TOK / 128), 256, SMEM>>>(
        hd, w4t, b_dec2, recon, nullptr, HD, HD);
}